// round 3
// baseline (speedup 1.0000x reference)
#include <cuda_runtime.h>

#define NTOK 8192
#define NMP  4096   // m-pairs
#define NT   32     // passB n-tile

typedef unsigned long long u64;

// Scratch (allocation-free rule: __device__ globals)
__device__ float d_F  [2 * NTOK * 8];   // f[n][k], plain
__device__ float d_GT2[2 * NTOK * 8];   // g pair-interleaved: [inp][mp][k][parity]
__device__ float d_VT [2 * NTOK * 64];  // v^T: vt[n][c]
__device__ float d_invden[2 * NTOK];

// ---- packed f32x2 helpers (sm_103a FFMA2 path; ptxas won't emit these) ----
__device__ __forceinline__ u64 pack2(float x, float y) {
    u64 r; asm("mov.b64 %0, {%1, %2};" : "=l"(r) : "f"(x), "f"(y)); return r;
}
__device__ __forceinline__ void unpack2(u64 v, float &x, float &y) {
    asm("mov.b64 {%0, %1}, %2;" : "=f"(x), "=f"(y) : "l"(v));
}
__device__ __forceinline__ void fma2(u64 &d, u64 a, u64 b) {
    asm("fma.rn.f32x2 %0, %1, %2, %0;" : "+l"(d) : "l"(a), "l"(b));
}
__device__ __forceinline__ u64 mul2(u64 a, u64 b) {
    u64 d; asm("mul.rn.f32x2 %0, %1, %2;" : "=l"(d) : "l"(a), "l"(b)); return d;
}

// ---------------------------------------------------------------------------
// Kernel 1: projections. grid (128, 2) x 256 threads; 64-token tile per block.
// tok = tid&63; og = tid>>6: all compute 16 v outputs; og0 -> f, og1 -> g.
// ---------------------------------------------------------------------------
__global__ __launch_bounds__(256) void proj_kernel(
    const float* __restrict__ x1, const float* __restrict__ x2,
    const float* __restrict__ Wf, const float* __restrict__ bf,
    const float* __restrict__ Wg, const float* __restrict__ bg,
    const float* __restrict__ Wh1, const float* __restrict__ bh1,
    const float* __restrict__ Wh2, const float* __restrict__ bh2)
{
    const int input = blockIdx.y;
    const float* __restrict__ x  = input ? x2  : x1;
    const float* __restrict__ Wh = input ? Wh2 : Wh1;
    const float* __restrict__ bh = input ? bh2 : bh1;

    __shared__ float x_s[64][65];
    __shared__ float Wh_s[64 * 64];
    __shared__ float Wfg_s[16 * 64];        // 8 f rows then 8 g rows
    __shared__ float bh_s[64], bfg_s[16];

    const int tid = threadIdx.x;
    for (int i = tid; i < 64 * 64; i += 256) Wh_s[i] = Wh[i];
    for (int i = tid; i < 16 * 64; i += 256) Wfg_s[i] = (i < 512) ? Wf[i] : Wg[i - 512];
    if (tid < 64) bh_s[tid] = bh[tid];
    if (tid < 16) bfg_s[tid] = (tid < 8) ? bf[tid] : bg[tid - 8];

    const int n0 = blockIdx.x * 64;
    for (int i = tid; i < 64 * 64; i += 256) {
        const int c = i >> 6, t = i & 63;
        x_s[c][t] = x[(size_t)c * NTOK + n0 + t];
    }
    __syncthreads();

    const int tok = tid & 63, og = tid >> 6;
    const int n = n0 + tok;

    float xr[64];
    #pragma unroll
    for (int c = 0; c < 64; c++) xr[c] = x_s[c][tok];

    // v: 16 outputs per thread, flushed as float4 groups
    float* VT = d_VT + (size_t)(input * NTOK + n) * 64 + og * 16;
    #pragma unroll
    for (int grp = 0; grp < 4; grp++) {
        float vo[4];
        #pragma unroll
        for (int u = 0; u < 4; u++) {
            const int o = og * 16 + grp * 4 + u;
            float a = bh_s[o];
            const float4* w4 = (const float4*)&Wh_s[o * 64];
            #pragma unroll
            for (int q = 0; q < 16; q++) {
                float4 w = w4[q];
                a = fmaf(w.x, xr[4*q+0], a); a = fmaf(w.y, xr[4*q+1], a);
                a = fmaf(w.z, xr[4*q+2], a); a = fmaf(w.w, xr[4*q+3], a);
            }
            vo[u] = a;
        }
        *(float4*)&VT[grp * 4] = make_float4(vo[0], vo[1], vo[2], vo[3]);
    }

    if (og < 2) {
        float fo[8];
        #pragma unroll
        for (int o8 = 0; o8 < 8; o8++) {
            const int o = og * 8 + o8;
            float a = bfg_s[o];
            const float4* w4 = (const float4*)&Wfg_s[o * 64];
            #pragma unroll
            for (int q = 0; q < 16; q++) {
                float4 w = w4[q];
                a = fmaf(w.x, xr[4*q+0], a); a = fmaf(w.y, xr[4*q+1], a);
                a = fmaf(w.z, xr[4*q+2], a); a = fmaf(w.w, xr[4*q+3], a);
            }
            fo[o8] = a;
        }
        if (og == 0) {
            float4* F = (float4*)&d_F[(size_t)(input * NTOK + n) * 8];
            F[0] = make_float4(fo[0], fo[1], fo[2], fo[3]);
            F[1] = make_float4(fo[4], fo[5], fo[6], fo[7]);
        } else {
            // pair-interleaved g: GT2[mp*16 + 2k + parity]
            float* G = d_GT2 + (size_t)input * NTOK * 8 + (size_t)(n >> 1) * 16 + (n & 1);
            #pragma unroll
            for (int k = 0; k < 8; k++) G[2 * k] = fo[k];
        }
    }
}

// ---------------------------------------------------------------------------
// Kernel 2: invden[n] = 1 / sum_m exp(f[n].g[m]).  grid (128,2) x 256.
// 64 n per block, 4 threads per n split over m. f32x2 logits on m-pairs.
// ---------------------------------------------------------------------------
__global__ __launch_bounds__(256) void passA_kernel()
{
    const int input = blockIdx.y;
    const int tid = threadIdx.x;
    const int nl = tid >> 2, sub = tid & 3;
    const int n = blockIdx.x * 64 + nl;

    u64 fp[8];
    {
        const float4* F4 = (const float4*)&d_F[(size_t)(input * NTOK + n) * 8];
        const float4 a = F4[0], b = F4[1];
        fp[0] = pack2(a.x, a.x); fp[1] = pack2(a.y, a.y);
        fp[2] = pack2(a.z, a.z); fp[3] = pack2(a.w, a.w);
        fp[4] = pack2(b.x, b.x); fp[5] = pack2(b.y, b.y);
        fp[6] = pack2(b.z, b.z); fp[7] = pack2(b.w, b.w);
    }

    __shared__ u64 gt2_s[32][8];
    const u64* GT64 = (const u64*)d_GT2 + (size_t)input * NMP * 8;

    float acc = 0.f;
    for (int mp0 = 0; mp0 < NMP; mp0 += 32) {
        __syncthreads();
        gt2_s[tid >> 3][tid & 7] = GT64[(size_t)(mp0 + (tid >> 3)) * 8 + (tid & 7)];
        __syncthreads();
        #pragma unroll
        for (int j = 0; j < 8; j++) {
            const int mp = sub + 4 * j;
            const ulonglong2* g = (const ulonglong2*)gt2_s[mp];
            const ulonglong2 g0 = g[0], g1 = g[1], g2 = g[2], g3 = g[3];
            u64 s = mul2(fp[0], g0.x);
            fma2(s, fp[1], g0.y); fma2(s, fp[2], g1.x); fma2(s, fp[3], g1.y);
            fma2(s, fp[4], g2.x); fma2(s, fp[5], g2.y);
            fma2(s, fp[6], g3.x); fma2(s, fp[7], g3.y);
            float s0, s1; unpack2(s, s0, s1);
            acc += __expf(s0) + __expf(s1);
        }
    }
    acc += __shfl_xor_sync(0xffffffffu, acc, 1);
    acc += __shfl_xor_sync(0xffffffffu, acc, 2);
    if (sub == 0) d_invden[input * NTOK + n] = 1.0f / acc;
}

// ---------------------------------------------------------------------------
// Kernel 3: y[c,m] = gamma * sum_n u[c,n] e[n,m] + x[c,m],  u = v*invden.
// grid (128, 2) x 128 threads. Block tile 64m x 64c, n-tile NT=32.
// Thread 4c x 8m (two quads 32 apart); FFMA2 main loop with pre-duplicated u.
// ---------------------------------------------------------------------------
__global__ __launch_bounds__(128) void passB_kernel(
    const float* __restrict__ x1, const float* __restrict__ x2,
    const float* __restrict__ g1, const float* __restrict__ g2,
    float* __restrict__ out)
{
    const int input = blockIdx.y;
    const float* __restrict__ x = input ? x2 : x1;
    const float gamma = input ? __ldg(g2) : __ldg(g1);

    const int m_base = blockIdx.x * 64;
    const int tid = threadIdx.x;
    const int cg = tid >> 3, mg = tid & 7;     // c0 = cg*4; m quads: mg*4, 32+mg*4
    const int c0 = cg * 4;
    const int enl = tid >> 2, q = tid & 3;     // e-construction roles

    __shared__ float u_dup[NT][128];           // (u,u) duplicated over c
    __shared__ float e_s[NT][64];
    __shared__ u64   gt2_s[32][8];

    const u64* GT64 = (const u64*)d_GT2 + (size_t)input * NMP * 8;
    for (int i = tid; i < 256; i += 128)
        gt2_s[i >> 3][i & 7] = GT64[(size_t)(m_base / 2 + (i >> 3)) * 8 + (i & 7)];

    u64 acc[4][4];
    #pragma unroll
    for (int i = 0; i < 4; i++)
        #pragma unroll
        for (int j = 0; j < 4; j++) acc[i][j] = 0ull;

    const float* VT  = d_VT + (size_t)input * NTOK * 64;
    const float* INV = d_invden + input * NTOK;

    for (int n0 = 0; n0 < NTOK; n0 += NT) {
        // f row for this thread's e-construction role (global load, hides latency)
        const float4* F4 = (const float4*)&d_F[(size_t)(input * NTOK + n0 + enl) * 8];
        const float4 fA = F4[0], fB = F4[1];
        u64 fp[8];
        fp[0] = pack2(fA.x, fA.x); fp[1] = pack2(fA.y, fA.y);
        fp[2] = pack2(fA.z, fA.z); fp[3] = pack2(fA.w, fA.w);
        fp[4] = pack2(fB.x, fB.x); fp[5] = pack2(fB.y, fB.y);
        fp[6] = pack2(fB.z, fB.z); fp[7] = pack2(fB.w, fB.w);

        __syncthreads();   // previous tile's reads complete

        // u tile, duplicated: u_dup[nl][2c] = u_dup[nl][2c+1] = v[c,n]*invden[n]
        #pragma unroll
        for (int k = 0; k < 16; k++) {
            const int i = tid + 128 * k;
            const int nl = i >> 6, c = i & 63;
            const float v = VT[(size_t)(n0 + nl) * 64 + c] * __ldg(&INV[n0 + nl]);
            *(float2*)&u_dup[nl][2 * c] = make_float2(v, v);
        }
        // e tile: e[nl][m] = exp(f . g), f32x2 pairs, mp rotated for bank-free STS
        #pragma unroll
        for (int j = 0; j < 8; j++) {
            const int mp = (q + 4 * j + 2 * enl) & 31;
            const ulonglong2* g = (const ulonglong2*)gt2_s[mp];
            const ulonglong2 g0 = g[0], g1 = g[1], g2v = g[2], g3 = g[3];
            u64 s = mul2(fp[0], g0.x);
            fma2(s, fp[1], g0.y); fma2(s, fp[2], g1.x); fma2(s, fp[3], g1.y);
            fma2(s, fp[4], g2v.x); fma2(s, fp[5], g2v.y);
            fma2(s, fp[6], g3.x); fma2(s, fp[7], g3.y);
            float s0, s1; unpack2(s, s0, s1);
            *(float2*)&e_s[enl][2 * mp] = make_float2(__expf(s0), __expf(s1));
        }
        __syncthreads();

        // main accumulation: per nl 4 LDS.128 + 16 FFMA2 (= 32 lane-FMA)
        #pragma unroll 8
        for (int nl = 0; nl < NT; nl++) {
            const ulonglong2* up = (const ulonglong2*)&u_dup[nl][2 * c0];
            const ulonglong2 u01 = up[0], u23 = up[1];
            const ulonglong2 ea = *(const ulonglong2*)&e_s[nl][mg * 4];
            const ulonglong2 eb = *(const ulonglong2*)&e_s[nl][32 + mg * 4];
            fma2(acc[0][0], u01.x, ea.x); fma2(acc[0][1], u01.x, ea.y);
            fma2(acc[0][2], u01.x, eb.x); fma2(acc[0][3], u01.x, eb.y);
            fma2(acc[1][0], u01.y, ea.x); fma2(acc[1][1], u01.y, ea.y);
            fma2(acc[1][2], u01.y, eb.x); fma2(acc[1][3], u01.y, eb.y);
            fma2(acc[2][0], u23.x, ea.x); fma2(acc[2][1], u23.x, ea.y);
            fma2(acc[2][2], u23.x, eb.x); fma2(acc[2][3], u23.x, eb.y);
            fma2(acc[3][0], u23.y, ea.x); fma2(acc[3][1], u23.y, ea.y);
            fma2(acc[3][2], u23.y, eb.x); fma2(acc[3][3], u23.y, eb.y);
        }
    }

    // epilogue: y = gamma * sa + x
    #pragma unroll
    for (int i = 0; i < 4; i++) {
        const int c = c0 + i;
        const size_t rowx = (size_t)c * NTOK;
        const size_t rowo = (size_t)(input * 64 + c) * NTOK;
        float a0, a1, a2, a3;
        unpack2(acc[i][0], a0, a1); unpack2(acc[i][1], a2, a3);
        const float4 xA = *(const float4*)&x[rowx + m_base + mg * 4];
        float4 yA;
        yA.x = fmaf(gamma, a0, xA.x); yA.y = fmaf(gamma, a1, xA.y);
        yA.z = fmaf(gamma, a2, xA.z); yA.w = fmaf(gamma, a3, xA.w);
        *(float4*)&out[rowo + m_base + mg * 4] = yA;

        unpack2(acc[i][2], a0, a1); unpack2(acc[i][3], a2, a3);
        const float4 xB = *(const float4*)&x[rowx + m_base + 32 + mg * 4];
        float4 yB;
        yB.x = fmaf(gamma, a0, xB.x); yB.y = fmaf(gamma, a1, xB.y);
        yB.z = fmaf(gamma, a2, xB.z); yB.w = fmaf(gamma, a3, xB.w);
        *(float4*)&out[rowo + m_base + 32 + mg * 4] = yB;
    }
}

// ---------------------------------------------------------------------------
extern "C" void kernel_launch(void* const* d_in, const int* in_sizes, int n_in,
                              void* d_out, int out_size)
{
    (void)in_sizes; (void)n_in; (void)out_size;
    const float* x1  = (const float*)d_in[0];
    const float* x2  = (const float*)d_in[1];
    const float* Wf  = (const float*)d_in[2];
    const float* bf  = (const float*)d_in[3];
    const float* Wg  = (const float*)d_in[4];
    const float* bg  = (const float*)d_in[5];
    const float* Wh1 = (const float*)d_in[6];
    const float* bh1 = (const float*)d_in[7];
    const float* Wh2 = (const float*)d_in[8];
    const float* bh2 = (const float*)d_in[9];
    const float* g1  = (const float*)d_in[10];
    const float* g2  = (const float*)d_in[11];
    float* out = (float*)d_out;

    dim3 gp(NTOK / 64, 2);
    proj_kernel<<<gp, 256>>>(x1, x2, Wf, bf, Wg, bg, Wh1, bh1, Wh2, bh2);
    dim3 ga(NTOK / 64, 2);
    passA_kernel<<<ga, 256>>>();
    dim3 gb(NTOK / 64, 2);
    passB_kernel<<<gb, 128>>>(x1, x2, g1, g2, out);
}

// round 6
// speedup vs baseline: 2.3927x; 2.3927x over previous
#include <cuda_runtime.h>
#include <cstdint>

#define NTOK 8192
#define KT   64            // passB n-chunk
#define CHUNKS (NTOK / KT) // 128

// smem layout (floats) for passB
#define GOFF   0            // g_s[128][8]
#define UOFF   1024         // u_s[64][72]
#define EOFF   (1024+4608)  // e_s[128][68]
#define STOFF  1024         // st_s[128][74] (epilogue, aliases u_s/e_s; EVEN stride -> float2-safe)
#define SMEM_FLOATS 14336   // 57344 bytes

// Scratch (allocation-free rule: __device__ globals)
__device__ float d_F [2 * NTOK * 8];
__device__ float d_GT[2 * NTOK * 8];
__device__ float d_VT[2 * NTOK * 64];
__device__ float d_invden[2 * NTOK];

__device__ __forceinline__ uint32_t to_tf32(float x) {
    uint32_t r; asm("cvt.rna.tf32.f32 %0, %1;" : "=r"(r) : "f"(x)); return r;
}
__device__ __forceinline__ void mma_tf32(float* d, uint32_t a0, uint32_t a1,
                                         uint32_t a2, uint32_t a3,
                                         uint32_t b0, uint32_t b1) {
    asm volatile(
        "mma.sync.aligned.m16n8k8.row.col.f32.tf32.tf32.f32 "
        "{%0,%1,%2,%3}, {%4,%5,%6,%7}, {%8,%9}, {%0,%1,%2,%3};"
        : "+f"(d[0]), "+f"(d[1]), "+f"(d[2]), "+f"(d[3])
        : "r"(a0), "r"(a1), "r"(a2), "r"(a3), "r"(b0), "r"(b1));
}

// ---------------------------------------------------------------------------
// Kernel 1 (R1, proven): projections f, g, v.  grid (64,2) x 128.
// ---------------------------------------------------------------------------
__global__ __launch_bounds__(128) void proj_kernel(
    const float* __restrict__ x1, const float* __restrict__ x2,
    const float* __restrict__ Wf, const float* __restrict__ bf,
    const float* __restrict__ Wg, const float* __restrict__ bg,
    const float* __restrict__ Wh1, const float* __restrict__ bh1,
    const float* __restrict__ Wh2, const float* __restrict__ bh2)
{
    const int input = blockIdx.y;
    const float* __restrict__ x  = input ? x2  : x1;
    const float* __restrict__ Wh = input ? Wh2 : Wh1;
    const float* __restrict__ bh = input ? bh2 : bh1;

    __shared__ float Wf_s[8 * 64], Wg_s[8 * 64], Wh_s[64 * 64];
    __shared__ float bf_s[8], bg_s[8], bh_s[64];
    __shared__ float v_s[32][129];

    const int tid = threadIdx.x;
    for (int i = tid; i < 8 * 64; i += 128) { Wf_s[i] = Wf[i]; Wg_s[i] = Wg[i]; }
    for (int i = tid; i < 64 * 64; i += 128) Wh_s[i] = Wh[i];
    if (tid < 8)  { bf_s[tid] = bf[tid]; bg_s[tid] = bg[tid]; }
    if (tid < 64) bh_s[tid] = bh[tid];
    __syncthreads();

    const int base = blockIdx.x * 128;
    const int n = base + tid;

    float xr[64];
    #pragma unroll
    for (int c = 0; c < 64; c++) xr[c] = x[c * NTOK + n];

    float fo[8], go[8];
    #pragma unroll
    for (int o = 0; o < 8; o++) {
        float af = bf_s[o], ag = bg_s[o];
        const float4* wf4 = (const float4*)&Wf_s[o * 64];
        const float4* wg4 = (const float4*)&Wg_s[o * 64];
        #pragma unroll
        for (int q = 0; q < 16; q++) {
            float4 wfv = wf4[q], wgv = wg4[q];
            af = fmaf(wfv.x, xr[4*q+0], af); af = fmaf(wfv.y, xr[4*q+1], af);
            af = fmaf(wfv.z, xr[4*q+2], af); af = fmaf(wfv.w, xr[4*q+3], af);
            ag = fmaf(wgv.x, xr[4*q+0], ag); ag = fmaf(wgv.y, xr[4*q+1], ag);
            ag = fmaf(wgv.z, xr[4*q+2], ag); ag = fmaf(wgv.w, xr[4*q+3], ag);
        }
        fo[o] = af; go[o] = ag;
    }
    {
        float4* Fo = (float4*)&d_F [(size_t)(input * NTOK + n) * 8];
        float4* Go = (float4*)&d_GT[(size_t)(input * NTOK + n) * 8];
        Fo[0] = make_float4(fo[0], fo[1], fo[2], fo[3]);
        Fo[1] = make_float4(fo[4], fo[5], fo[6], fo[7]);
        Go[0] = make_float4(go[0], go[1], go[2], go[3]);
        Go[1] = make_float4(go[4], go[5], go[6], go[7]);
    }

    #pragma unroll
    for (int half = 0; half < 2; half++) {
        #pragma unroll
        for (int o2 = 0; o2 < 32; o2++) {
            const int o = half * 32 + o2;
            float a = bh_s[o];
            const float4* wh4 = (const float4*)&Wh_s[o * 64];
            #pragma unroll
            for (int q = 0; q < 16; q++) {
                float4 w = wh4[q];
                a = fmaf(w.x, xr[4*q+0], a); a = fmaf(w.y, xr[4*q+1], a);
                a = fmaf(w.z, xr[4*q+2], a); a = fmaf(w.w, xr[4*q+3], a);
            }
            v_s[o2][tid] = a;
        }
        __syncthreads();
        for (int i = tid; i < 128 * 32; i += 128) {
            const int nl = i >> 5, o2 = i & 31;
            d_VT[(size_t)(input * NTOK + base + nl) * 64 + half * 32 + o2] = v_s[o2][nl];
        }
        __syncthreads();
    }
}

// ---------------------------------------------------------------------------
// Kernel 2 (R1, proven): invden.  grid (128,2) x 256.
// ---------------------------------------------------------------------------
__global__ __launch_bounds__(256) void passA_kernel()
{
    const int input = blockIdx.y;
    const int tid = threadIdx.x;
    const int sub = tid & 3;
    const int n = blockIdx.x * 64 + (tid >> 2);

    const float4* F4  = (const float4*)d_F;
    const float4* GT4 = (const float4*)d_GT;
    const float4 fa = F4[(size_t)(input * NTOK + n) * 2 + 0];
    const float4 fb = F4[(size_t)(input * NTOK + n) * 2 + 1];

    __shared__ float4 gt_s[64][2];

    float acc = 0.f;
    for (int m0 = 0; m0 < NTOK; m0 += 64) {
        __syncthreads();
        if (tid < 128) {
            gt_s[tid >> 1][tid & 1] =
                GT4[(size_t)(input * NTOK + m0 + (tid >> 1)) * 2 + (tid & 1)];
        }
        __syncthreads();
        #pragma unroll
        for (int k = 0; k < 16; k++) {
            const int ml = (k << 2) + sub;
            const float4 ga = gt_s[ml][0], gb = gt_s[ml][1];
            float s = fa.x * ga.x;
            s = fmaf(fa.y, ga.y, s); s = fmaf(fa.z, ga.z, s); s = fmaf(fa.w, ga.w, s);
            s = fmaf(fb.x, gb.x, s); s = fmaf(fb.y, gb.y, s);
            s = fmaf(fb.z, gb.z, s); s = fmaf(fb.w, gb.w, s);
            acc += __expf(s);
        }
    }
    acc += __shfl_xor_sync(0xffffffffu, acc, 1);
    acc += __shfl_xor_sync(0xffffffffu, acc, 2);
    if (sub == 0) d_invden[input * NTOK + n] = 1.0f / acc;
}

// ---------------------------------------------------------------------------
// Kernel 3: passB via tf32 mma.sync.
//   D[m, c] = sum_n e^T[m,n] * u[n,c];  y[c,m] = gamma*D + x[c,m]
// grid (64, 2) x 256 (8 warps). m-tile 128, c 64, n-chunks of 64.
// Warp w owns m-slab [w*16, w*16+16), all 64 c (8 c-tiles), acc[8][4].
// ---------------------------------------------------------------------------
__global__ __launch_bounds__(256) void passB_kernel(
    const float* __restrict__ x1, const float* __restrict__ x2,
    const float* __restrict__ g1, const float* __restrict__ g2,
    float* __restrict__ out)
{
    extern __shared__ float smf[];
    float*    g_s = smf + GOFF;                 // [128][8]
    uint32_t* u_s = (uint32_t*)(smf + UOFF);    // [64][72] tf32 bits
    uint32_t* e_s = (uint32_t*)(smf + EOFF);    // [128][68] tf32 bits
    float*    st_s = smf + STOFF;               // [128][74] epilogue (even stride)

    const int tid = threadIdx.x;
    const int wid = tid >> 5, lane = tid & 31;
    const int g4 = lane >> 2, q4 = lane & 3;
    const int input = blockIdx.y;
    const int m_base = blockIdx.x * 128;

    // g tile for this block (once)
    {
        const float* src = d_GT + (size_t)input * NTOK * 8 + (size_t)m_base * 8;
        for (int i = tid; i < 128 * 8; i += 256) g_s[i] = src[i];
    }

    // roles
    const int n_e = tid & 63, mgrp = tid >> 6;  // e-gen: token n_e, m-group
    const float* VT  = d_VT + (size_t)input * NTOK * 64;
    const float* INV = d_invden + input * NTOK;
    const float4* Fb = (const float4*)(d_F + (size_t)input * NTOK * 8);

    float acc[8][4];
    #pragma unroll
    for (int t = 0; t < 8; t++)
        #pragma unroll
        for (int r = 0; r < 4; r++) acc[t][r] = 0.f;

    // prefetch chunk 0 operands
    float4 fA = Fb[(size_t)n_e * 2], fB = Fb[(size_t)n_e * 2 + 1];
    float4 vv[4]; float iv[4];
    #pragma unroll
    for (int k = 0; k < 4; k++) {
        const int idx = tid + 256 * k;
        const int n = idx >> 4, c4 = idx & 15;
        vv[k] = ((const float4*)VT)[(size_t)n * 16 + c4];
        iv[k] = INV[n];
    }
    __syncthreads();

    for (int chunk = 0; chunk < CHUNKS; chunk++) {
        const int n0 = chunk * KT;

        // ---- u tile: u[n][c] = tf32(v * invden) ----
        #pragma unroll
        for (int k = 0; k < 4; k++) {
            const int idx = tid + 256 * k;
            const int n = idx >> 4, c4 = idx & 15;
            uint4 p;
            p.x = to_tf32(vv[k].x * iv[k]); p.y = to_tf32(vv[k].y * iv[k]);
            p.z = to_tf32(vv[k].z * iv[k]); p.w = to_tf32(vv[k].w * iv[k]);
            *(uint4*)&u_s[n * 72 + c4 * 4] = p;
        }
        // ---- e tile: e[m][n_e] = tf32(exp(f . g)) ----
        #pragma unroll 8
        for (int j = 0; j < 32; j++) {
            const int m = mgrp * 32 + j;
            const float4 ga = *(const float4*)&g_s[m * 8];
            const float4 gb = *(const float4*)&g_s[m * 8 + 4];
            float s = fA.x * ga.x;
            s = fmaf(fA.y, ga.y, s); s = fmaf(fA.z, ga.z, s); s = fmaf(fA.w, ga.w, s);
            s = fmaf(fB.x, gb.x, s); s = fmaf(fB.y, gb.y, s);
            s = fmaf(fB.z, gb.z, s); s = fmaf(fB.w, gb.w, s);
            e_s[m * 68 + n_e] = to_tf32(__expf(s));
        }

        // prefetch next chunk operands (overlaps with MMA phase)
        if (chunk + 1 < CHUNKS) {
            const int nn = n0 + KT;
            fA = Fb[(size_t)(nn + n_e) * 2]; fB = Fb[(size_t)(nn + n_e) * 2 + 1];
            #pragma unroll
            for (int k = 0; k < 4; k++) {
                const int idx = tid + 256 * k;
                const int n = idx >> 4, c4 = idx & 15;
                vv[k] = ((const float4*)VT)[(size_t)(nn + n) * 16 + c4];
                iv[k] = INV[nn + n];
            }
        }
        __syncthreads();

        // ---- GEMM2: warp slab m = wid*16.. , 8 k-steps x 8 c-tiles ----
        const int mrow = wid * 16;
        #pragma unroll
        for (int kk = 0; kk < 8; kk++) {
            const uint32_t a0 = e_s[(mrow + g4)     * 68 + kk * 8 + q4];
            const uint32_t a1 = e_s[(mrow + g4 + 8) * 68 + kk * 8 + q4];
            const uint32_t a2 = e_s[(mrow + g4)     * 68 + kk * 8 + q4 + 4];
            const uint32_t a3 = e_s[(mrow + g4 + 8) * 68 + kk * 8 + q4 + 4];
            #pragma unroll
            for (int ct = 0; ct < 8; ct++) {
                const uint32_t b0 = u_s[(kk * 8 + q4)     * 72 + ct * 8 + g4];
                const uint32_t b1 = u_s[(kk * 8 + q4 + 4) * 72 + ct * 8 + g4];
                mma_tf32(acc[ct], a0, a1, a2, a3, b0, b1);
            }
        }
        __syncthreads();
    }

    // ---- epilogue: stage D to smem [m][c] (stride 74, float2-safe), then coalesced y ----
    {
        const int mrow = wid * 16;
        #pragma unroll
        for (int ct = 0; ct < 8; ct++) {
            const int c = ct * 8 + q4 * 2;
            *(float2*)&st_s[(mrow + g4)     * 74 + c] = make_float2(acc[ct][0], acc[ct][1]);
            *(float2*)&st_s[(mrow + g4 + 8) * 74 + c] = make_float2(acc[ct][2], acc[ct][3]);
        }
    }
    __syncthreads();
    {
        const float* __restrict__ x = input ? x2 : x1;
        const float gamma = input ? __ldg(g2) : __ldg(g1);
        #pragma unroll
        for (int w8 = 0; w8 < 8; w8++) {
            const int c = wid + 8 * w8;
            const size_t rowx = (size_t)c * NTOK + m_base;
            const size_t rowo = (size_t)(input * 64 + c) * NTOK + m_base;
            #pragma unroll
            for (int jj = 0; jj < 4; jj++) {
                const int m = lane + 32 * jj;
                out[rowo + m] = fmaf(gamma, st_s[m * 74 + c], x[rowx + m]);
            }
        }
    }
}

// ---------------------------------------------------------------------------
extern "C" void kernel_launch(void* const* d_in, const int* in_sizes, int n_in,
                              void* d_out, int out_size)
{
    (void)in_sizes; (void)n_in; (void)out_size;
    const float* x1  = (const float*)d_in[0];
    const float* x2  = (const float*)d_in[1];
    const float* Wf  = (const float*)d_in[2];
    const float* bf  = (const float*)d_in[3];
    const float* Wg  = (const float*)d_in[4];
    const float* bg  = (const float*)d_in[5];
    const float* Wh1 = (const float*)d_in[6];
    const float* bh1 = (const float*)d_in[7];
    const float* Wh2 = (const float*)d_in[8];
    const float* bh2 = (const float*)d_in[9];
    const float* g1  = (const float*)d_in[10];
    const float* g2  = (const float*)d_in[11];
    float* out = (float*)d_out;

    cudaFuncSetAttribute(passB_kernel, cudaFuncAttributeMaxDynamicSharedMemorySize,
                         SMEM_FLOATS * 4);

    dim3 gp(NTOK / 128, 2);
    proj_kernel<<<gp, 128>>>(x1, x2, Wf, bf, Wg, bg, Wh1, bh1, Wh2, bh2);
    dim3 ga(NTOK / 64, 2);
    passA_kernel<<<ga, 256>>>();
    dim3 gb(NTOK / 128, 2);
    passB_kernel<<<gb, 256, SMEM_FLOATS * 4>>>(x1, x2, g1, g2, out);
}

// round 7
// speedup vs baseline: 3.5909x; 1.5007x over previous
#include <cuda_runtime.h>
#include <cstdint>

#define NTOK 8192
#define KT   64            // passB n-chunk
#define CHUNKS (NTOK / KT) // 128

// smem layout (floats) for passB
#define GOFF   0            // g_s[128][8]
#define UOFF   1024         // u_s[64][72] (tf32 bits)
#define EOFF   (1024+4608)  // e_s[128][68] (tf32 bits)
#define STOFF  1024         // st_s[128][74] epilogue (aliases u/e; even stride)
#define SMEM_FLOATS 14336   // 57344 bytes

// Scratch (allocation-free rule: __device__ globals)
__device__ float d_F [2 * NTOK * 8];
__device__ float d_GT[2 * NTOK * 8];
__device__ float d_VT[2 * NTOK * 64];
__device__ float d_invden[2 * NTOK];

__device__ __forceinline__ uint32_t to_tf32(float x) {
    uint32_t r; asm("cvt.rna.tf32.f32 %0, %1;" : "=r"(r) : "f"(x)); return r;
}
__device__ __forceinline__ void mma_tf32(float* d, uint32_t a0, uint32_t a1,
                                         uint32_t a2, uint32_t a3,
                                         uint32_t b0, uint32_t b1) {
    asm volatile(
        "mma.sync.aligned.m16n8k8.row.col.f32.tf32.tf32.f32 "
        "{%0,%1,%2,%3}, {%4,%5,%6,%7}, {%8,%9}, {%0,%1,%2,%3};"
        : "+f"(d[0]), "+f"(d[1]), "+f"(d[2]), "+f"(d[3])
        : "r"(a0), "r"(a1), "r"(a2), "r"(a3), "r"(b0), "r"(b1));
}

// ---------------------------------------------------------------------------
// Kernel 1 (R2 structure, 26us measured): projections.  grid (128,2) x 256.
// 64-token tile; tok = tid&63, og = tid>>6: all 4 og compute 16 v outputs;
// og0 -> f, og1 -> g (plain layouts).
// ---------------------------------------------------------------------------
__global__ __launch_bounds__(256) void proj_kernel(
    const float* __restrict__ x1, const float* __restrict__ x2,
    const float* __restrict__ Wf, const float* __restrict__ bf,
    const float* __restrict__ Wg, const float* __restrict__ bg,
    const float* __restrict__ Wh1, const float* __restrict__ bh1,
    const float* __restrict__ Wh2, const float* __restrict__ bh2)
{
    const int input = blockIdx.y;
    const float* __restrict__ x  = input ? x2  : x1;
    const float* __restrict__ Wh = input ? Wh2 : Wh1;
    const float* __restrict__ bh = input ? bh2 : bh1;

    __shared__ float x_s[64][65];
    __shared__ float Wh_s[64 * 64];
    __shared__ float Wfg_s[16 * 64];
    __shared__ float bh_s[64], bfg_s[16];

    const int tid = threadIdx.x;
    for (int i = tid; i < 64 * 64; i += 256) Wh_s[i] = Wh[i];
    for (int i = tid; i < 16 * 64; i += 256) Wfg_s[i] = (i < 512) ? Wf[i] : Wg[i - 512];
    if (tid < 64) bh_s[tid] = bh[tid];
    if (tid < 16) bfg_s[tid] = (tid < 8) ? bf[tid] : bg[tid - 8];

    const int n0 = blockIdx.x * 64;
    for (int i = tid; i < 64 * 64; i += 256) {
        const int c = i >> 6, t = i & 63;
        x_s[c][t] = x[(size_t)c * NTOK + n0 + t];
    }
    __syncthreads();

    const int tok = tid & 63, og = tid >> 6;
    const int n = n0 + tok;

    float xr[64];
    #pragma unroll
    for (int c = 0; c < 64; c++) xr[c] = x_s[c][tok];

    float* VT = d_VT + (size_t)(input * NTOK + n) * 64 + og * 16;
    #pragma unroll
    for (int grp = 0; grp < 4; grp++) {
        float vo[4];
        #pragma unroll
        for (int u = 0; u < 4; u++) {
            const int o = og * 16 + grp * 4 + u;
            float a = bh_s[o];
            const float4* w4 = (const float4*)&Wh_s[o * 64];
            #pragma unroll
            for (int q = 0; q < 16; q++) {
                float4 w = w4[q];
                a = fmaf(w.x, xr[4*q+0], a); a = fmaf(w.y, xr[4*q+1], a);
                a = fmaf(w.z, xr[4*q+2], a); a = fmaf(w.w, xr[4*q+3], a);
            }
            vo[u] = a;
        }
        *(float4*)&VT[grp * 4] = make_float4(vo[0], vo[1], vo[2], vo[3]);
    }

    if (og < 2) {
        float fo[8];
        #pragma unroll
        for (int o8 = 0; o8 < 8; o8++) {
            const int o = og * 8 + o8;
            float a = bfg_s[o];
            const float4* w4 = (const float4*)&Wfg_s[o * 64];
            #pragma unroll
            for (int q = 0; q < 16; q++) {
                float4 w = w4[q];
                a = fmaf(w.x, xr[4*q+0], a); a = fmaf(w.y, xr[4*q+1], a);
                a = fmaf(w.z, xr[4*q+2], a); a = fmaf(w.w, xr[4*q+3], a);
            }
            fo[o8] = a;
        }
        float4* dst = (og == 0) ? (float4*)&d_F [(size_t)(input * NTOK + n) * 8]
                                : (float4*)&d_GT[(size_t)(input * NTOK + n) * 8];
        dst[0] = make_float4(fo[0], fo[1], fo[2], fo[3]);
        dst[1] = make_float4(fo[4], fo[5], fo[6], fo[7]);
    }
}

// ---------------------------------------------------------------------------
// Kernel 2: invden via tf32 MMA logits.  grid (128,2) x 128 (4 warps).
// Warp w owns n-rows [n0 + w*16, +16); loop m in chunks of 64 (8 n8-tiles).
// ---------------------------------------------------------------------------
__global__ __launch_bounds__(128) void passA_kernel()
{
    const int input = blockIdx.y;
    const int tid = threadIdx.x;
    const int wid = tid >> 5, lane = tid & 31;
    const int g4 = lane >> 2, q4 = lane & 3;
    const int nr = blockIdx.x * 64 + wid * 16;

    const float* F = d_F + (size_t)(input * NTOK + nr) * 8;
    const uint32_t a0 = to_tf32(F[ g4      * 8 + q4]);
    const uint32_t a1 = to_tf32(F[(g4 + 8) * 8 + q4]);
    const uint32_t a2 = to_tf32(F[ g4      * 8 + q4 + 4]);
    const uint32_t a3 = to_tf32(F[(g4 + 8) * 8 + q4 + 4]);

    const float* G = d_GT + (size_t)input * NTOK * 8;
    float sum0 = 0.f, sum1 = 0.f;

    for (int m0 = 0; m0 < NTOK; m0 += 64) {
        #pragma unroll
        for (int t = 0; t < 8; t++) {
            const float* gp = G + (size_t)(m0 + t * 8 + g4) * 8;
            const uint32_t b0 = to_tf32(__ldg(gp + q4));
            const uint32_t b1 = to_tf32(__ldg(gp + q4 + 4));
            float d[4] = {0.f, 0.f, 0.f, 0.f};
            mma_tf32(d, a0, a1, a2, a3, b0, b1);
            sum0 += __expf(d[0]) + __expf(d[1]);
            sum1 += __expf(d[2]) + __expf(d[3]);
        }
    }
    sum0 += __shfl_xor_sync(0xffffffffu, sum0, 1);
    sum0 += __shfl_xor_sync(0xffffffffu, sum0, 2);
    sum1 += __shfl_xor_sync(0xffffffffu, sum1, 1);
    sum1 += __shfl_xor_sync(0xffffffffu, sum1, 2);
    if (q4 == 0) {
        d_invden[input * NTOK + nr + g4]     = 1.0f / sum0;
        d_invden[input * NTOK + nr + g4 + 8] = 1.0f / sum1;
    }
}

// ---------------------------------------------------------------------------
// Kernel 3: passB via tf32 mma.sync, 512 threads (16 warps) for latency hiding.
//   D[m, c] = sum_n e^T[m,n] * u[n,c];  y[c,m] = gamma*D + x[c,m]
// grid (64, 2) x 512. m-tile 128, c 64, n-chunks of 64.
// Warp w: m-slab (w&7)*16, c-half (w>>3)*32 (4 c-tiles), acc[4][4].
// ---------------------------------------------------------------------------
__global__ __launch_bounds__(512) void passB_kernel(
    const float* __restrict__ x1, const float* __restrict__ x2,
    const float* __restrict__ g1, const float* __restrict__ g2,
    float* __restrict__ out)
{
    extern __shared__ float smf[];
    float*    g_s  = smf + GOFF;                // [128][8]
    uint32_t* u_s  = (uint32_t*)(smf + UOFF);   // [64][72] tf32 bits
    uint32_t* e_s  = (uint32_t*)(smf + EOFF);   // [128][68] tf32 bits
    float*    st_s = smf + STOFF;               // [128][74] epilogue

    const int tid = threadIdx.x;
    const int wid = tid >> 5, lane = tid & 31;
    const int g4 = lane >> 2, q4 = lane & 3;
    const int input = blockIdx.y;
    const int m_base = blockIdx.x * 128;

    {
        const float* src = d_GT + (size_t)input * NTOK * 8 + (size_t)m_base * 8;
        for (int i = tid; i < 128 * 8; i += 512) g_s[i] = src[i];
    }

    // roles
    const int n_e = tid & 63, mgrp = tid >> 6;        // e-gen
    const float* VT  = d_VT + (size_t)input * NTOK * 64;
    const float* INV = d_invden + input * NTOK;
    const float4* Fb = (const float4*)(d_F + (size_t)input * NTOK * 8);

    float acc[4][4];
    #pragma unroll
    for (int t = 0; t < 4; t++)
        #pragma unroll
        for (int r = 0; r < 4; r++) acc[t][r] = 0.f;

    // prefetch chunk 0 operands
    float4 fA = Fb[(size_t)n_e * 2], fB = Fb[(size_t)n_e * 2 + 1];
    float4 vv[2]; float iv[2];
    #pragma unroll
    for (int k = 0; k < 2; k++) {
        const int idx = tid + 512 * k;
        const int n = idx >> 4, c4 = idx & 15;
        vv[k] = ((const float4*)VT)[(size_t)n * 16 + c4];
        iv[k] = INV[n];
    }
    __syncthreads();

    for (int chunk = 0; chunk < CHUNKS; chunk++) {
        const int n0 = chunk * KT;

        // ---- u tile: u[n][c] = tf32(v * invden) ----
        #pragma unroll
        for (int k = 0; k < 2; k++) {
            const int idx = tid + 512 * k;
            const int n = idx >> 4, c4 = idx & 15;
            uint4 p;
            p.x = to_tf32(vv[k].x * iv[k]); p.y = to_tf32(vv[k].y * iv[k]);
            p.z = to_tf32(vv[k].z * iv[k]); p.w = to_tf32(vv[k].w * iv[k]);
            *(uint4*)&u_s[n * 72 + c4 * 4] = p;
        }
        // ---- e tile: e[m][n_e] = tf32(exp(f . g)), 16 m per thread ----
        #pragma unroll 8
        for (int j = 0; j < 16; j++) {
            const int m = mgrp * 16 + j;
            const float4 ga = *(const float4*)&g_s[m * 8];
            const float4 gb = *(const float4*)&g_s[m * 8 + 4];
            float s = fA.x * ga.x;
            s = fmaf(fA.y, ga.y, s); s = fmaf(fA.z, ga.z, s); s = fmaf(fA.w, ga.w, s);
            s = fmaf(fB.x, gb.x, s); s = fmaf(fB.y, gb.y, s);
            s = fmaf(fB.z, gb.z, s); s = fmaf(fB.w, gb.w, s);
            e_s[m * 68 + n_e] = to_tf32(__expf(s));
        }

        // prefetch next chunk operands
        if (chunk + 1 < CHUNKS) {
            const int nn = n0 + KT;
            fA = Fb[(size_t)(nn + n_e) * 2]; fB = Fb[(size_t)(nn + n_e) * 2 + 1];
            #pragma unroll
            for (int k = 0; k < 2; k++) {
                const int idx = tid + 512 * k;
                const int n = idx >> 4, c4 = idx & 15;
                vv[k] = ((const float4*)VT)[(size_t)(nn + n) * 16 + c4];
                iv[k] = INV[nn + n];
            }
        }
        __syncthreads();

        // ---- GEMM2: warp slab m=(wid&7)*16, c-tiles (wid>>3)*4 + 0..3 ----
        const int mrow = (wid & 7) * 16;
        const int cb = (wid >> 3) * 4;
        #pragma unroll
        for (int kk = 0; kk < 8; kk++) {
            const uint32_t a0 = e_s[(mrow + g4)     * 68 + kk * 8 + q4];
            const uint32_t a1 = e_s[(mrow + g4 + 8) * 68 + kk * 8 + q4];
            const uint32_t a2 = e_s[(mrow + g4)     * 68 + kk * 8 + q4 + 4];
            const uint32_t a3 = e_s[(mrow + g4 + 8) * 68 + kk * 8 + q4 + 4];
            #pragma unroll
            for (int ct = 0; ct < 4; ct++) {
                const uint32_t b0 = u_s[(kk * 8 + q4)     * 72 + (cb + ct) * 8 + g4];
                const uint32_t b1 = u_s[(kk * 8 + q4 + 4) * 72 + (cb + ct) * 8 + g4];
                mma_tf32(acc[ct], a0, a1, a2, a3, b0, b1);
            }
        }
        __syncthreads();
    }

    // ---- epilogue: stage D to smem [m][c] (stride 74), then coalesced y ----
    {
        const int mrow = (wid & 7) * 16;
        const int cb = (wid >> 3) * 4;
        #pragma unroll
        for (int ct = 0; ct < 4; ct++) {
            const int c = (cb + ct) * 8 + q4 * 2;
            *(float2*)&st_s[(mrow + g4)     * 74 + c] = make_float2(acc[ct][0], acc[ct][1]);
            *(float2*)&st_s[(mrow + g4 + 8) * 74 + c] = make_float2(acc[ct][2], acc[ct][3]);
        }
    }
    __syncthreads();
    {
        const float* __restrict__ x = input ? x2 : x1;
        const float gamma = input ? __ldg(g2) : __ldg(g1);
        #pragma unroll
        for (int w8 = 0; w8 < 4; w8++) {
            const int c = wid + 16 * w8;
            const size_t rowx = (size_t)c * NTOK + m_base;
            const size_t rowo = (size_t)(input * 64 + c) * NTOK + m_base;
            #pragma unroll
            for (int jj = 0; jj < 4; jj++) {
                const int m = lane + 32 * jj;
                out[rowo + m] = fmaf(gamma, st_s[m * 74 + c], x[rowx + m]);
            }
        }
    }
}

// ---------------------------------------------------------------------------
extern "C" void kernel_launch(void* const* d_in, const int* in_sizes, int n_in,
                              void* d_out, int out_size)
{
    (void)in_sizes; (void)n_in; (void)out_size;
    const float* x1  = (const float*)d_in[0];
    const float* x2  = (const float*)d_in[1];
    const float* Wf  = (const float*)d_in[2];
    const float* bf  = (const float*)d_in[3];
    const float* Wg  = (const float*)d_in[4];
    const float* bg  = (const float*)d_in[5];
    const float* Wh1 = (const float*)d_in[6];
    const float* bh1 = (const float*)d_in[7];
    const float* Wh2 = (const float*)d_in[8];
    const float* bh2 = (const float*)d_in[9];
    const float* g1  = (const float*)d_in[10];
    const float* g2  = (const float*)d_in[11];
    float* out = (float*)d_out;

    cudaFuncSetAttribute(passB_kernel, cudaFuncAttributeMaxDynamicSharedMemorySize,
                         SMEM_FLOATS * 4);

    dim3 gp(NTOK / 64, 2);
    proj_kernel<<<gp, 256>>>(x1, x2, Wf, bf, Wg, bg, Wh1, bh1, Wh2, bh2);
    dim3 ga(NTOK / 64, 2);
    passA_kernel<<<ga, 128>>>();
    dim3 gb(NTOK / 128, 2);
    passB_kernel<<<gb, 512, SMEM_FLOATS * 4>>>(x1, x2, g1, g2, out);
}

// round 8
// speedup vs baseline: 3.7201x; 1.0360x over previous
#include <cuda_runtime.h>
#include <cstdint>

#define NTOK 8192
#define KT   64            // passB n-chunk
#define CHUNKS (NTOK / KT) // 128

// passB smem layout (float indices)
#define GOFF   0                 // g_s[128][8]                 -> 1024
#define UOFF   1024              // u_s[2][64*72]               -> +9216 = 10240
#define UBUF   4608
#define EOFF   10240             // e_s[2][128*68]              -> +17408 = 27648
#define EBUF   8704
#define STOFF  1024              // st_s[128][74] (epilogue alias, even stride)
#define SMEM_FLOATS 27648        // 110592 bytes

// Scratch (allocation-free rule: __device__ globals)
__device__ float d_F [2 * NTOK * 8];
__device__ float d_GT[2 * NTOK * 8];
__device__ float d_VT[2 * NTOK * 64];
__device__ float d_invden[2 * NTOK];

__device__ __forceinline__ uint32_t to_tf32(float x) {
    uint32_t r; asm("cvt.rna.tf32.f32 %0, %1;" : "=r"(r) : "f"(x)); return r;
}
__device__ __forceinline__ void mma_tf32(float* d, uint32_t a0, uint32_t a1,
                                         uint32_t a2, uint32_t a3,
                                         uint32_t b0, uint32_t b1) {
    asm volatile(
        "mma.sync.aligned.m16n8k8.row.col.f32.tf32.tf32.f32 "
        "{%0,%1,%2,%3}, {%4,%5,%6,%7}, {%8,%9}, {%0,%1,%2,%3};"
        : "+f"(d[0]), "+f"(d[1]), "+f"(d[2]), "+f"(d[3])
        : "r"(a0), "r"(a1), "r"(a2), "r"(a3), "r"(b0), "r"(b1));
}
__device__ __forceinline__ void ldsm_x4(uint32_t& r0, uint32_t& r1,
                                        uint32_t& r2, uint32_t& r3, uint32_t addr) {
    asm volatile("ldmatrix.sync.aligned.m8n8.x4.shared.b16 {%0,%1,%2,%3}, [%4];"
                 : "=r"(r0), "=r"(r1), "=r"(r2), "=r"(r3) : "r"(addr));
}
__device__ __forceinline__ uint32_t smem_u32(const void* p) {
    uint32_t a;
    asm("{ .reg .u64 t; cvta.to.shared.u64 t, %1; cvt.u32.u64 %0, t; }" : "=r"(a) : "l"(p));
    return a;
}

// ---------------------------------------------------------------------------
// Kernel 1 (proven, 26us): projections.  grid (128,2) x 256.
// ---------------------------------------------------------------------------
__global__ __launch_bounds__(256) void proj_kernel(
    const float* __restrict__ x1, const float* __restrict__ x2,
    const float* __restrict__ Wf, const float* __restrict__ bf,
    const float* __restrict__ Wg, const float* __restrict__ bg,
    const float* __restrict__ Wh1, const float* __restrict__ bh1,
    const float* __restrict__ Wh2, const float* __restrict__ bh2)
{
    const int input = blockIdx.y;
    const float* __restrict__ x  = input ? x2  : x1;
    const float* __restrict__ Wh = input ? Wh2 : Wh1;
    const float* __restrict__ bh = input ? bh2 : bh1;

    __shared__ float x_s[64][65];
    __shared__ float Wh_s[64 * 64];
    __shared__ float Wfg_s[16 * 64];
    __shared__ float bh_s[64], bfg_s[16];

    const int tid = threadIdx.x;
    for (int i = tid; i < 64 * 64; i += 256) Wh_s[i] = Wh[i];
    for (int i = tid; i < 16 * 64; i += 256) Wfg_s[i] = (i < 512) ? Wf[i] : Wg[i - 512];
    if (tid < 64) bh_s[tid] = bh[tid];
    if (tid < 16) bfg_s[tid] = (tid < 8) ? bf[tid] : bg[tid - 8];

    const int n0 = blockIdx.x * 64;
    for (int i = tid; i < 64 * 64; i += 256) {
        const int c = i >> 6, t = i & 63;
        x_s[c][t] = x[(size_t)c * NTOK + n0 + t];
    }
    __syncthreads();

    const int tok = tid & 63, og = tid >> 6;
    const int n = n0 + tok;

    float xr[64];
    #pragma unroll
    for (int c = 0; c < 64; c++) xr[c] = x_s[c][tok];

    float* VT = d_VT + (size_t)(input * NTOK + n) * 64 + og * 16;
    #pragma unroll
    for (int grp = 0; grp < 4; grp++) {
        float vo[4];
        #pragma unroll
        for (int u = 0; u < 4; u++) {
            const int o = og * 16 + grp * 4 + u;
            float a = bh_s[o];
            const float4* w4 = (const float4*)&Wh_s[o * 64];
            #pragma unroll
            for (int q = 0; q < 16; q++) {
                float4 w = w4[q];
                a = fmaf(w.x, xr[4*q+0], a); a = fmaf(w.y, xr[4*q+1], a);
                a = fmaf(w.z, xr[4*q+2], a); a = fmaf(w.w, xr[4*q+3], a);
            }
            vo[u] = a;
        }
        *(float4*)&VT[grp * 4] = make_float4(vo[0], vo[1], vo[2], vo[3]);
    }

    if (og < 2) {
        float fo[8];
        #pragma unroll
        for (int o8 = 0; o8 < 8; o8++) {
            const int o = og * 8 + o8;
            float a = bfg_s[o];
            const float4* w4 = (const float4*)&Wfg_s[o * 64];
            #pragma unroll
            for (int q = 0; q < 16; q++) {
                float4 w = w4[q];
                a = fmaf(w.x, xr[4*q+0], a); a = fmaf(w.y, xr[4*q+1], a);
                a = fmaf(w.z, xr[4*q+2], a); a = fmaf(w.w, xr[4*q+3], a);
            }
            fo[o8] = a;
        }
        float4* dst = (og == 0) ? (float4*)&d_F [(size_t)(input * NTOK + n) * 8]
                                : (float4*)&d_GT[(size_t)(input * NTOK + n) * 8];
        dst[0] = make_float4(fo[0], fo[1], fo[2], fo[3]);
        dst[1] = make_float4(fo[4], fo[5], fo[6], fo[7]);
    }
}

// ---------------------------------------------------------------------------
// Kernel 2: invden via tf32 MMA logits.  grid (64,2) x 256 (8 warps).
// ---------------------------------------------------------------------------
__global__ __launch_bounds__(256) void passA_kernel()
{
    const int input = blockIdx.y;
    const int tid = threadIdx.x;
    const int wid = tid >> 5, lane = tid & 31;
    const int g4 = lane >> 2, q4 = lane & 3;
    const int nr = blockIdx.x * 128 + wid * 16;

    const float* F = d_F + (size_t)(input * NTOK + nr) * 8;
    const uint32_t a0 = to_tf32(F[ g4      * 8 + q4]);
    const uint32_t a1 = to_tf32(F[(g4 + 8) * 8 + q4]);
    const uint32_t a2 = to_tf32(F[ g4      * 8 + q4 + 4]);
    const uint32_t a3 = to_tf32(F[(g4 + 8) * 8 + q4 + 4]);

    const float* G = d_GT + (size_t)input * NTOK * 8;
    float sum0 = 0.f, sum1 = 0.f;

    for (int m0 = 0; m0 < NTOK; m0 += 64) {
        #pragma unroll
        for (int t = 0; t < 8; t++) {
            const float* gp = G + (size_t)(m0 + t * 8 + g4) * 8;
            const uint32_t b0 = to_tf32(__ldg(gp + q4));
            const uint32_t b1 = to_tf32(__ldg(gp + q4 + 4));
            float d[4] = {0.f, 0.f, 0.f, 0.f};
            mma_tf32(d, a0, a1, a2, a3, b0, b1);
            sum0 += __expf(d[0]) + __expf(d[1]);
            sum1 += __expf(d[2]) + __expf(d[3]);
        }
    }
    sum0 += __shfl_xor_sync(0xffffffffu, sum0, 1);
    sum0 += __shfl_xor_sync(0xffffffffu, sum0, 2);
    sum1 += __shfl_xor_sync(0xffffffffu, sum1, 1);
    sum1 += __shfl_xor_sync(0xffffffffu, sum1, 2);
    if (q4 == 0) {
        d_invden[input * NTOK + nr + g4]     = 1.0f / sum0;
        d_invden[input * NTOK + nr + g4 + 8] = 1.0f / sum1;
    }
}

// ---------------------------------------------------------------------------
// Kernel 3: passB, tf32 mma.sync, double-buffered (gen(k+1) overlaps mma(k)),
// A-fragments via ldmatrix.x4.  grid (64,2) x 512.
// ---------------------------------------------------------------------------
__global__ __launch_bounds__(512) void passB_kernel(
    const float* __restrict__ x1, const float* __restrict__ x2,
    const float* __restrict__ g1, const float* __restrict__ g2,
    float* __restrict__ out)
{
    extern __shared__ float smf[];
    float*    g_s  = smf + GOFF;
    uint32_t* u_s  = (uint32_t*)(smf + UOFF);   // [2][64*72]
    uint32_t* e_s  = (uint32_t*)(smf + EOFF);   // [2][128*68]
    float*    st_s = smf + STOFF;

    const int tid = threadIdx.x;
    const int wid = tid >> 5, lane = tid & 31;
    const int g4 = lane >> 2, q4 = lane & 3;
    const int input = blockIdx.y;
    const int m_base = blockIdx.x * 128;

    {
        const float* src = d_GT + (size_t)input * NTOK * 8 + (size_t)m_base * 8;
        for (int i = tid; i < 128 * 8; i += 512) g_s[i] = src[i];
    }

    const int n_e = tid & 63, mgrp = tid >> 6;        // e-gen roles
    const float* VT  = d_VT + (size_t)input * NTOK * 64;
    const float* INV = d_invden + input * NTOK;
    const float4* Fb = (const float4*)(d_F + (size_t)input * NTOK * 8);

    const int mrow = (wid & 7) * 16;
    const int cb = (wid >> 3) * 4;

    // ldmatrix per-lane row address base (byte offset inside one e-buffer)
    const uint32_t e_smaddr = smem_u32(e_s);
    const uint32_t a_row = (uint32_t)(mrow + (lane & 7) + (((lane >> 3) & 1) << 3));
    const uint32_t a_base_off = (a_row * 68u + ((lane >> 4) << 2)) * 4u;

    float acc[4][4];
    #pragma unroll
    for (int t = 0; t < 4; t++)
        #pragma unroll
        for (int r = 0; r < 4; r++) acc[t][r] = 0.f;

    float4 fA, fB, vv[2]; float iv[2];

    // ---- helpers as macros ----
#define LOADG(ch)                                                              \
    {                                                                          \
        const int nn = (ch) * KT;                                              \
        fA = Fb[(size_t)(nn + n_e) * 2]; fB = Fb[(size_t)(nn + n_e) * 2 + 1];  \
        _Pragma("unroll")                                                      \
        for (int k = 0; k < 2; k++) {                                          \
            const int idx = tid + 512 * k;                                     \
            const int n = idx >> 4, c4 = idx & 15;                             \
            vv[k] = ((const float4*)VT)[(size_t)(nn + n) * 16 + c4];           \
            iv[k] = INV[nn + n];                                               \
        }                                                                      \
    }

#define GENSTORE(bufi)                                                         \
    {                                                                          \
        uint32_t* ub = u_s + (bufi) * UBUF;                                    \
        uint32_t* eb = e_s + (bufi) * EBUF;                                    \
        _Pragma("unroll")                                                      \
        for (int k = 0; k < 2; k++) {                                          \
            const int idx = tid + 512 * k;                                     \
            const int n = idx >> 4, c4 = idx & 15;                             \
            uint4 p;                                                           \
            p.x = to_tf32(vv[k].x * iv[k]); p.y = to_tf32(vv[k].y * iv[k]);    \
            p.z = to_tf32(vv[k].z * iv[k]); p.w = to_tf32(vv[k].w * iv[k]);    \
            *(uint4*)&ub[n * 72 + c4 * 4] = p;                                 \
        }                                                                      \
        _Pragma("unroll")                                                      \
        for (int j = 0; j < 16; j++) {                                         \
            const int m = mgrp * 16 + j;                                       \
            const float4 ga = *(const float4*)&g_s[m * 8];                     \
            const float4 gb = *(const float4*)&g_s[m * 8 + 4];                 \
            float s = fA.x * ga.x;                                             \
            s = fmaf(fA.y, ga.y, s); s = fmaf(fA.z, ga.z, s);                  \
            s = fmaf(fA.w, ga.w, s);                                           \
            s = fmaf(fB.x, gb.x, s); s = fmaf(fB.y, gb.y, s);                  \
            s = fmaf(fB.z, gb.z, s); s = fmaf(fB.w, gb.w, s);                  \
            eb[m * 68 + n_e] = to_tf32(__expf(s));                             \
        }                                                                      \
    }

    // prologue: fill buffer 0
    LOADG(0);
    GENSTORE(0);
    LOADG(1);
    __syncthreads();

    for (int chunk = 0; chunk < CHUNKS; chunk++) {
        const int buf = chunk & 1;

        // produce next chunk into the other buffer (overlaps with MMA below)
        if (chunk + 1 < CHUNKS) {
            GENSTORE(buf ^ 1);
            if (chunk + 2 < CHUNKS) LOADG(chunk + 2);
        }

        // MMA on current buffer
        {
            const uint32_t* ub = u_s + buf * UBUF;
            const uint32_t abase = e_smaddr + (uint32_t)(buf * EBUF * 4) + a_base_off;
            #pragma unroll
            for (int kk = 0; kk < 8; kk++) {
                uint32_t a0, a1, a2, a3;
                ldsm_x4(a0, a1, a2, a3, abase + kk * 32u);
                #pragma unroll
                for (int ct = 0; ct < 4; ct++) {
                    const uint32_t b0 = ub[(kk * 8 + q4)     * 72 + (cb + ct) * 8 + g4];
                    const uint32_t b1 = ub[(kk * 8 + q4 + 4) * 72 + (cb + ct) * 8 + g4];
                    mma_tf32(acc[ct], a0, a1, a2, a3, b0, b1);
                }
            }
        }
        __syncthreads();
    }
#undef LOADG
#undef GENSTORE

    // ---- epilogue: stage D to smem [m][c] (stride 74), then coalesced y ----
    #pragma unroll
    for (int ct = 0; ct < 4; ct++) {
        const int c = (cb + ct) * 8 + q4 * 2;
        *(float2*)&st_s[(mrow + g4)     * 74 + c] = make_float2(acc[ct][0], acc[ct][1]);
        *(float2*)&st_s[(mrow + g4 + 8) * 74 + c] = make_float2(acc[ct][2], acc[ct][3]);
    }
    __syncthreads();
    {
        const float* __restrict__ x = input ? x2 : x1;
        const float gamma = input ? __ldg(g2) : __ldg(g1);
        #pragma unroll
        for (int w8 = 0; w8 < 4; w8++) {
            const int c = wid + 16 * w8;
            const size_t rowx = (size_t)c * NTOK + m_base;
            const size_t rowo = (size_t)(input * 64 + c) * NTOK + m_base;
            #pragma unroll
            for (int jj = 0; jj < 4; jj++) {
                const int m = lane + 32 * jj;
                out[rowo + m] = fmaf(gamma, st_s[m * 74 + c], x[rowx + m]);
            }
        }
    }
}

// ---------------------------------------------------------------------------
extern "C" void kernel_launch(void* const* d_in, const int* in_sizes, int n_in,
                              void* d_out, int out_size)
{
    (void)in_sizes; (void)n_in; (void)out_size;
    const float* x1  = (const float*)d_in[0];
    const float* x2  = (const float*)d_in[1];
    const float* Wf  = (const float*)d_in[2];
    const float* bf  = (const float*)d_in[3];
    const float* Wg  = (const float*)d_in[4];
    const float* bg  = (const float*)d_in[5];
    const float* Wh1 = (const float*)d_in[6];
    const float* bh1 = (const float*)d_in[7];
    const float* Wh2 = (const float*)d_in[8];
    const float* bh2 = (const float*)d_in[9];
    const float* g1  = (const float*)d_in[10];
    const float* g2  = (const float*)d_in[11];
    float* out = (float*)d_out;

    cudaFuncSetAttribute(passB_kernel, cudaFuncAttributeMaxDynamicSharedMemorySize,
                         SMEM_FLOATS * 4);

    dim3 gp(NTOK / 64, 2);
    proj_kernel<<<gp, 256>>>(x1, x2, Wf, bf, Wg, bg, Wh1, bh1, Wh2, bh2);
    dim3 ga(NTOK / 128, 2);
    passA_kernel<<<ga, 256>>>();
    dim3 gb(NTOK / 128, 2);
    passB_kernel<<<gb, 512, SMEM_FLOATS * 4>>>(x1, x2, g1, g2, out);
}